// round 9
// baseline (speedup 1.0000x reference)
#include <cuda_runtime.h>
#include <cuda_bf16.h>
#include <cstdint>

// Shapes (fixed by problem)
#define Bv 4
#define Sv 512
#define Hv 256

// Scratch (device globals: no allocation allowed in kernel_launch)
__device__ float g_P[(Bv * Sv) * (2 * Hv)];   // [m][0:256]=h@W_t, [256:512]=h@W_t' + b_h   (4 MB)
__device__ float g_S[Bv * Sv * Sv];           // sigmoid(scores)                              (4 MB)
__device__ float g_AW[Bv * Sv * Sv];          // softmax(attention weights)                   (4 MB)

__device__ __forceinline__ float fast_tanh(float x) {
    float y;
    asm("tanh.approx.f32 %0, %1;" : "=f"(y) : "f"(x));
    return y;
}

// ---------------------------------------------------------------------------
// Kernel 1: fused projection GEMM
//   C[M=2048][N=512] = h[2048][256] @ [W_t | W_t'] ;  cols >=256 get +b_h
// Tiles: 64x64, BK=32, 256 threads, 4x4 microtile.
// ---------------------------------------------------------------------------
__global__ __launch_bounds__(256) void k1_proj(
    const float* __restrict__ h,
    const float* __restrict__ Wt,
    const float* __restrict__ Wtp,
    const float* __restrict__ bh)
{
    __shared__ float sA[64][33];
    __shared__ float sB[32][65];
    const int tid = threadIdx.x;
    const int bm = blockIdx.y * 64;
    const int bn = blockIdx.x * 64;
    const int tx = tid & 15, ty = tid >> 4;

    float acc[4][4] = {};
    for (int k0 = 0; k0 < Hv; k0 += 32) {
        #pragma unroll
        for (int i = 0; i < 8; i++) {
            int idx = tid + i * 256;
            int r = idx >> 5, c = idx & 31;
            sA[r][c] = h[(bm + r) * Hv + k0 + c];
        }
        #pragma unroll
        for (int i = 0; i < 8; i++) {
            int idx = tid + i * 256;
            int r = idx >> 6, c = idx & 63;
            int n = bn + c;
            const float* W = (n < Hv) ? Wt : Wtp;
            sB[r][c] = W[(k0 + r) * Hv + (n & (Hv - 1))];
        }
        __syncthreads();
        #pragma unroll
        for (int k = 0; k < 32; k++) {
            float a[4], b[4];
            #pragma unroll
            for (int i = 0; i < 4; i++) a[i] = sA[ty * 4 + i][k];
            #pragma unroll
            for (int j = 0; j < 4; j++) b[j] = sB[k][tx * 4 + j];
            #pragma unroll
            for (int i = 0; i < 4; i++)
                #pragma unroll
                for (int j = 0; j < 4; j++)
                    acc[i][j] = fmaf(a[i], b[j], acc[i][j]);
        }
        __syncthreads();
    }
    #pragma unroll
    for (int i = 0; i < 4; i++) {
        int m = bm + ty * 4 + i;
        #pragma unroll
        for (int j = 0; j < 4; j++) {
            int n = bn + tx * 4 + j;
            float v = acc[i][j];
            if (n >= Hv) v += bh[n - Hv];
            g_P[m * (2 * Hv) + n] = v;
        }
    }
}

// ---------------------------------------------------------------------------
// Kernel 2: pairwise scores (the MUFU-bound kernel)
//   S[b,t,t'] = sigmoid( b_a + sum_h W_a[h] * tanh(ht[b,t,h] + htp[b,t',h]) )
// 32x32 score tile per block, h chunked by 64, 2x2 microtile per thread.
// Per h-step/thread: 5 LDS + 4 FADD + 4 MUFU.TANH + 4 FFMA -> MUFU-bound.
// ---------------------------------------------------------------------------
#define TT 32
#define HC 64
__global__ __launch_bounds__(256) void k2_scores(
    const float* __restrict__ Wa,
    const float* __restrict__ ba)
{
    __shared__ float sA[TT][HC + 1];
    __shared__ float sB[TT][HC + 1];
    __shared__ float sW[HC];

    const int b   = blockIdx.z;
    const int t0  = blockIdx.y * TT;
    const int tp0 = blockIdx.x * TT;
    const int tid = threadIdx.x;
    const int tx = tid & 15, ty = tid >> 4;

    const float* Pb = g_P + (size_t)b * Sv * (2 * Hv);

    float acc00 = 0.f, acc01 = 0.f, acc10 = 0.f, acc11 = 0.f;

    for (int h0 = 0; h0 < Hv; h0 += HC) {
        #pragma unroll
        for (int i = 0; i < 8; i++) {
            int idx = tid + i * 256;
            int r = idx >> 6, c = idx & 63;
            sA[r][c] = Pb[(t0  + r) * (2 * Hv) + h0 + c];          // ht rows
            sB[r][c] = Pb[(tp0 + r) * (2 * Hv) + Hv + h0 + c];     // htp+b_h rows
        }
        if (tid < HC) sW[tid] = Wa[h0 + tid];
        __syncthreads();

        #pragma unroll
        for (int hh = 0; hh < HC; hh++) {
            float w  = sW[hh];
            float a0 = sA[2 * ty][hh];
            float a1 = sA[2 * ty + 1][hh];
            float b0 = sB[2 * tx][hh];
            float b1 = sB[2 * tx + 1][hh];
            acc00 = fmaf(w, fast_tanh(a0 + b0), acc00);
            acc01 = fmaf(w, fast_tanh(a0 + b1), acc01);
            acc10 = fmaf(w, fast_tanh(a1 + b0), acc10);
            acc11 = fmaf(w, fast_tanh(a1 + b1), acc11);
        }
        __syncthreads();
    }

    const float bav = ba[0];
    float* Sb = g_S + (size_t)b * Sv * Sv;
    float r[2][2] = {{acc00, acc01}, {acc10, acc11}};
    #pragma unroll
    for (int i = 0; i < 2; i++) {
        #pragma unroll
        for (int j = 0; j < 2; j++) {
            float x = r[i][j] + bav;
            float sg = 1.0f / (1.0f + __expf(-x));
            Sb[(t0 + 2 * ty + i) * Sv + (tp0 + 2 * tx + j)] = sg;
        }
    }
}

// ---------------------------------------------------------------------------
// Kernel 3: row softmax. One warp per row of 512 (float4 vectorized).
// Writes g_AW always; mirrors into d_out's attention-weights region if given.
// ---------------------------------------------------------------------------
__global__ __launch_bounds__(256) void k3_softmax(float* __restrict__ aw_out)
{
    const int row  = blockIdx.x * 8 + (threadIdx.x >> 5);
    const int lane = threadIdx.x & 31;
    const float4* src = (const float4*)(g_S + (size_t)row * Sv);

    float4 v[4];
    float mx = -1e30f;
    #pragma unroll
    for (int i = 0; i < 4; i++) {
        v[i] = src[i * 32 + lane];
        mx = fmaxf(mx, fmaxf(fmaxf(v[i].x, v[i].y), fmaxf(v[i].z, v[i].w)));
    }
    #pragma unroll
    for (int o = 16; o > 0; o >>= 1)
        mx = fmaxf(mx, __shfl_xor_sync(0xffffffffu, mx, o));

    float sum = 0.f;
    #pragma unroll
    for (int i = 0; i < 4; i++) {
        v[i].x = __expf(v[i].x - mx);
        v[i].y = __expf(v[i].y - mx);
        v[i].z = __expf(v[i].z - mx);
        v[i].w = __expf(v[i].w - mx);
        sum += v[i].x + v[i].y + v[i].z + v[i].w;
    }
    #pragma unroll
    for (int o = 16; o > 0; o >>= 1)
        sum += __shfl_xor_sync(0xffffffffu, sum, o);

    const float inv = 1.0f / sum;
    float4* dst = (float4*)(g_AW + (size_t)row * Sv);
    #pragma unroll
    for (int i = 0; i < 4; i++) {
        float4 o4 = v[i];
        o4.x *= inv; o4.y *= inv; o4.z *= inv; o4.w *= inv;
        dst[i * 32 + lane] = o4;
    }
    if (aw_out) {
        float4* dst2 = (float4*)(aw_out + (size_t)row * Sv);
        #pragma unroll
        for (int i = 0; i < 4; i++) {
            float4 o4 = v[i];
            o4.x *= inv; o4.y *= inv; o4.z *= inv; o4.w *= inv;
            dst2[i * 32 + lane] = o4;
        }
    }
}

// ---------------------------------------------------------------------------
// Kernel 4: output[b] = AW[b](512x512) @ h[b](512x256). Tiled fp32 GEMM.
// 64x64 tiles, BK=32, 256 threads, 4x4 microtile. Grid 4x8x4 = 128 blocks.
// ---------------------------------------------------------------------------
__global__ __launch_bounds__(256) void k4_out(
    const float* __restrict__ h,
    float* __restrict__ out)
{
    __shared__ float sA[64][33];
    __shared__ float sB[32][65];
    const int b   = blockIdx.z;
    const int bm  = blockIdx.y * 64;   // t rows
    const int bn  = blockIdx.x * 64;   // h cols
    const int tid = threadIdx.x;
    const int tx = tid & 15, ty = tid >> 4;

    const float* A = g_AW + (size_t)b * Sv * Sv;   // 512x512
    const float* Bm = h + (size_t)b * Sv * Hv;     // 512x256
    float* C = out + (size_t)b * Sv * Hv;

    float acc[4][4] = {};
    for (int k0 = 0; k0 < Sv; k0 += 32) {
        #pragma unroll
        for (int i = 0; i < 8; i++) {
            int idx = tid + i * 256;
            int r = idx >> 5, c = idx & 31;
            sA[r][c] = A[(bm + r) * Sv + k0 + c];
        }
        #pragma unroll
        for (int i = 0; i < 8; i++) {
            int idx = tid + i * 256;
            int r = idx >> 6, c = idx & 63;
            sB[r][c] = Bm[(k0 + r) * Hv + bn + c];
        }
        __syncthreads();
        #pragma unroll
        for (int k = 0; k < 32; k++) {
            float a[4], bb[4];
            #pragma unroll
            for (int i = 0; i < 4; i++) a[i] = sA[ty * 4 + i][k];
            #pragma unroll
            for (int j = 0; j < 4; j++) bb[j] = sB[k][tx * 4 + j];
            #pragma unroll
            for (int i = 0; i < 4; i++)
                #pragma unroll
                for (int j = 0; j < 4; j++)
                    acc[i][j] = fmaf(a[i], bb[j], acc[i][j]);
        }
        __syncthreads();
    }
    #pragma unroll
    for (int i = 0; i < 4; i++) {
        int m = bm + ty * 4 + i;
        #pragma unroll
        for (int j = 0; j < 4; j++)
            C[m * Hv + bn + tx * 4 + j] = acc[i][j];
    }
}

// ---------------------------------------------------------------------------
extern "C" void kernel_launch(void* const* d_in, const int* in_sizes, int n_in,
                              void* d_out, int out_size)
{
    const float* h   = (const float*)d_in[0];  // (4,512,256)
    const float* Wt  = (const float*)d_in[1];  // (256,256)
    const float* Wtp = (const float*)d_in[2];  // (256,256)
    const float* bh  = (const float*)d_in[3];  // (256,)
    const float* Wa  = (const float*)d_in[4];  // (256,)
    const float* ba  = (const float*)d_in[5];  // ()

    float* out = (float*)d_out;
    const int out_elems = Bv * Sv * Hv;        // 524288
    const int aw_elems  = Bv * Sv * Sv;        // 1048576
    float* aw_out = (out_size >= out_elems + aw_elems) ? out + out_elems : nullptr;

    // k1: projections  C[2048][512]
    {
        dim3 grid((2 * Hv) / 64, (Bv * Sv) / 64);   // 8 x 32
        k1_proj<<<grid, 256>>>(h, Wt, Wtp, bh);
    }
    // k2: pairwise tanh scores + sigmoid
    {
        dim3 grid(Sv / TT, Sv / TT, Bv);            // 16 x 16 x 4
        k2_scores<<<grid, 256>>>(Wa, ba);
    }
    // k3: softmax rows
    {
        k3_softmax<<<(Bv * Sv) / 8, 256>>>(aw_out);
    }
    // k4: output = AW @ h
    {
        dim3 grid(Hv / 64, Sv / 64, Bv);            // 4 x 8 x 4
        k4_out<<<grid, 256>>>(h, out);
    }
}